// round 3
// baseline (speedup 1.0000x reference)
#include <cuda_runtime.h>

#define HW   16384
#define NB   2
#define CIN  128
#define CO   64
#define NK   64
#define NPIX (NB*HW)

// accumulator pack
#define ACC_SUMS  0        // 8192 floats: [b][k][o]
#define ACC_CNT   8192     // 128 floats:  [b][k]
#define ACC_BNSUM 8320     // 64
#define ACC_BNSQ  8384     // 64
#define ACCN      8448

// ---------------- scratch (static device globals; zero-initialized by loader) ----------------
__device__ float g_xt[(size_t)NPIX*CO];      // [b][hw][o] pixel-major, 8 MB (L2-resident)
__device__ float g_acc[ACCN];
__device__ float g_invcov[CO*CO];
__device__ float g_means[NB*NK*CO];
__device__ float g_T[NB*NK*CO];
__device__ float g_diag[NB*NK];
__device__ float g_adjm[NB*NK*CO];

// ---------------- helpers ----------------
__device__ __forceinline__ unsigned long long pk2(float v) {
    unsigned long long r; unsigned u = __float_as_uint(v);
    asm("mov.b64 %0, {%1, %2};" : "=l"(r) : "r"(u), "r"(u));
    return r;
}
__device__ __forceinline__ void ffma2(unsigned long long& d,
                                      unsigned long long a, unsigned long long b) {
    asm("fma.rn.f32x2 %0, %1, %2, %3;" : "=l"(d) : "l"(a), "l"(b), "l"(d));
}
__device__ __forceinline__ void red4(float* p, float a, float b, float c, float d) {
    asm volatile("red.add.v4.f32 [%0], {%1, %2, %3, %4};"
                 :: "l"(p), "f"(a), "f"(b), "f"(c), "f"(d) : "memory");
}
__device__ __forceinline__ void cpa16(float* sdst, const float* gsrc) {
    unsigned saddr = (unsigned)__cvta_generic_to_shared(sdst);
    asm volatile("cp.async.ca.shared.global [%0], [%1], 16;" :: "r"(saddr), "l"(gsrc));
}
__device__ __forceinline__ void cpa_commit() {
    asm volatile("cp.async.commit_group;");
}
template<int N> __device__ __forceinline__ void cpa_wait() {
    asm volatile("cp.async.wait_group %0;" :: "n"(N));
}

// ---------------- Kernel 1: GEMM (blocks 0..127, cp.async pipelined) + inverse (block 128) ----------------
__global__ __launch_bounds__(256) void k_main(const float* __restrict__ x,
                                              const float* __restrict__ Wft,
                                              const int*   __restrict__ idx,
                                              const float* __restrict__ Wm) {
    __shared__ float sm[8448];   // 33 KB union
    const int tid = threadIdx.x;

    if (blockIdx.x == 128) {
        // ---- zero BN accumulators for this run (consumed only after k_main) ----
        if (tid < 128) g_acc[ACC_BNSUM + tid] = 0.f;
        // ---- inv(Wm Wm^T), Gauss-Jordan, SPD ----
        float* aug  = sm;          // 64 x 128
        float* colp = sm + 8192;   // 64
        float* prow = sm + 8256;   // 128
        for (int e = tid; e < 4096; e += 256) {
            int i = e >> 6, j = e & 63;
            float s = 0.f;
            for (int c = 0; c < 64; c += 4) {
                float4 a  = *(const float4*)(Wm + i*64 + c);
                float4 bb = *(const float4*)(Wm + j*64 + c);
                s += a.x*bb.x + a.y*bb.y + a.z*bb.z + a.w*bb.w;
            }
            aug[i*128 + j]      = s;
            aug[i*128 + 64 + j] = (i == j) ? 1.f : 0.f;
        }
        __syncthreads();
        for (int p = 0; p < 64; p++) {
            if (tid < 64) {
                colp[tid] = aug[tid*128 + p];
            } else if (tid < 192) {
                int j = tid - 64;
                prow[j] = aug[p*128 + j] * (1.f / aug[p*128 + p]);
            }
            __syncthreads();
            for (int e = tid; e < 8192; e += 256) {
                int i = e >> 7, j = e & 127;
                float pr = prow[j];
                aug[e] = (i == p) ? pr : fmaf(-colp[i], pr, aug[e]);
            }
            __syncthreads();
        }
        for (int e = tid; e < 4096; e += 256)
            g_invcov[e] = aug[(e>>6)*128 + 64 + (e&63)];
        return;
    }

    // ---- GEMM path: 256 px x 64 out, double-buffered cp.async ----
    float* xs   = sm;                 // 2 x 2048 floats
    float* ws   = sm + 4096;          // 2 x 512
    float* scnt = sm + 5120;          // 64
    int*   sidx = (int*)(sm + 5184);  // 256

    const int P0  = blockIdx.x * 256;
    const int b   = P0 >> 14;
    const int hw0 = P0 & (HW-1);
    const float* xb = x + (size_t)b*CIN*HW + hw0;

    if (tid < 64) {
        scnt[tid] = 0.f;
        ((int4*)sidx)[tid] = ((const int4*)(idx + P0))[tid];
    }

    const int chg = tid & 7;     // 8 channel groups of 8
    const int pxg = tid >> 3;    // 32 pixel groups of 8
    unsigned long long acc2[8][4];
#pragma unroll
    for (int i = 0; i < 8; i++)
#pragma unroll
        for (int j = 0; j < 4; j++) acc2[i][j] = 0ull;

    // issue tile t into buffer buf
    const int r0a = tid >> 6,        c0a = (tid & 63) * 4;       // rows 0..3
    const int r0b = (tid >> 6) + 4,  c0b = c0a;                  // rows 4..7
    {
        // prefetch tile 0
        float* xd = xs;
        cpa16(xd + r0a*256 + c0a, xb + (size_t)r0a*HW + c0a);
        cpa16(xd + r0b*256 + c0b, xb + (size_t)r0b*HW + c0b);
        if (tid < 128) cpa16(ws + tid*4, Wft + tid*4);
        cpa_commit();
    }

    for (int t = 0; t < 16; t++) {
        const int buf = t & 1;
        if (t < 15) {
            float* xd = xs + (buf^1)*2048;
            const float* src = xb + (size_t)(t+1)*8*HW;
            cpa16(xd + r0a*256 + c0a, src + (size_t)r0a*HW + c0a);
            cpa16(xd + r0b*256 + c0b, src + (size_t)r0b*HW + c0b);
            if (tid < 128) cpa16(ws + (buf^1)*512 + tid*4, Wft + (size_t)(t+1)*8*CO + tid*4);
            cpa_commit();
            cpa_wait<1>();
        } else {
            cpa_wait<0>();
        }
        __syncthreads();
        const float* xsb = xs + buf*2048;
        const float* wsb = ws + buf*512;
#pragma unroll
        for (int cc = 0; cc < 8; cc++) {
            float xv[8];
            *(float4*)(xv)   = *(const float4*)(xsb + cc*256 + pxg*8);
            *(float4*)(xv+4) = *(const float4*)(xsb + cc*256 + pxg*8 + 4);
            ulonglong2 wA = *(const ulonglong2*)(wsb + cc*64 + chg*8);
            ulonglong2 wB = *(const ulonglong2*)(wsb + cc*64 + chg*8 + 4);
#pragma unroll
            for (int i = 0; i < 8; i++) {
                unsigned long long ax = pk2(xv[i]);
                ffma2(acc2[i][0], ax, wA.x);
                ffma2(acc2[i][1], ax, wA.y);
                ffma2(acc2[i][2], ax, wB.x);
                ffma2(acc2[i][3], ax, wB.y);
            }
        }
        __syncthreads();   // compute(buf) done before iter t+1 overwrites buf
    }

    float* ob = g_xt + ((size_t)b*HW + hw0)*CO;
#pragma unroll
    for (int i = 0; i < 8; i++) {
        int px = pxg*8 + i;
        unsigned long long a0 = acc2[i][0], a1 = acc2[i][1],
                           a2 = acc2[i][2], a3 = acc2[i][3];
        float v0 = __uint_as_float((unsigned)a0), v1 = __uint_as_float((unsigned)(a0>>32));
        float v2 = __uint_as_float((unsigned)a1), v3 = __uint_as_float((unsigned)(a1>>32));
        float v4 = __uint_as_float((unsigned)a2), v5 = __uint_as_float((unsigned)(a2>>32));
        float v6 = __uint_as_float((unsigned)a3), v7 = __uint_as_float((unsigned)(a3>>32));
        *(float4*)(ob + (size_t)px*CO + chg*8)     = make_float4(v0,v1,v2,v3);
        *(float4*)(ob + (size_t)px*CO + chg*8 + 4) = make_float4(v4,v5,v6,v7);
        int k = sidx[px];
        float* sp = g_acc + ACC_SUMS + ((b*NK + k)*CO + chg*8);
        red4(sp,     v0,v1,v2,v3);
        red4(sp + 4, v4,v5,v6,v7);
        if (chg == 0) atomicAdd(&scnt[k], 1.f);
    }
    __syncthreads();
    if (tid < 64) atomicAdd(&g_acc[ACC_CNT + b*64 + tid], scnt[tid]);
}

// ---------------- Kernel 2: means, T = means*invcov, diag ----------------
__global__ __launch_bounds__(256) void k_adjA() {
    __shared__ float As[4096], mR[512], tR[512];
    const int tid = threadIdx.x;
    const int b = blockIdx.x >> 3, r0 = (blockIdx.x & 7) * 8;

    for (int e = tid; e < 1024; e += 256)
        ((float4*)As)[e] = ((const float4*)g_invcov)[e];
    for (int e = tid; e < 512; e += 256) {
        int rl = e >> 6;
        float c = g_acc[ACC_CNT + b*64 + r0 + rl];
        float v = g_acc[ACC_SUMS + b*4096 + r0*64 + e] / ((c > 0.f) ? c : 1.f);
        mR[e] = v;
        g_means[b*4096 + r0*64 + e] = v;
    }
    __syncthreads();
    {
        int il0 = tid >> 6, j = tid & 63, il1 = il0 + 4;
        float a0 = 0.f, a1 = 0.f;
        for (int c = 0; c < 64; c++) {
            float Ac = As[c*64 + j];
            a0 = fmaf(mR[il0*64 + c], Ac, a0);
            a1 = fmaf(mR[il1*64 + c], Ac, a1);
        }
        tR[il0*64 + j] = a0;  tR[il1*64 + j] = a1;
        g_T[b*4096 + (r0+il0)*64 + j] = a0;
        g_T[b*4096 + (r0+il1)*64 + j] = a1;
    }
    __syncthreads();
    if (tid < 8) {
        float d = 0.f;
        for (int c = 0; c < 64; c++)
            d = fmaf(tR[tid*64 + c], mR[tid*64 + c], d);
        g_diag[b*64 + r0 + tid] = d;
    }
}

// ---------------- Kernel 3: G -> adj = exp(-sqrt(q)) -> adjm = adj*means ----------------
__global__ __launch_bounds__(256) void k_adjB() {
    __shared__ float Ms[4096];      // mean[j][c] at Ms[c*64 + (j^(c&31))]
    __shared__ float tRb[512], sadj[512], dg[64];
    const int tid = threadIdx.x;
    const int b = blockIdx.x >> 3, r0 = (blockIdx.x & 7) * 8;

    for (int e = tid; e < 4096; e += 256) {
        int j = e >> 6, c = e & 63;
        Ms[c*64 + (j ^ (c & 31))] = g_means[b*4096 + e];
    }
    for (int e = tid; e < 512; e += 256)
        tRb[e] = g_T[b*4096 + r0*64 + e];
    if (tid < 64) dg[tid] = g_diag[b*64 + tid];
    __syncthreads();
    {
        int il0 = tid >> 6, j = tid & 63, il1 = il0 + 4;
        float a0 = 0.f, a1 = 0.f;
        for (int c = 0; c < 64; c++) {
            float mv = Ms[c*64 + (j ^ (c & 31))];
            a0 = fmaf(tRb[il0*64 + c], mv, a0);
            a1 = fmaf(tRb[il1*64 + c], mv, a1);
        }
        float q0 = dg[r0+il0] + dg[j] - 2.f*a0;
        float q1 = dg[r0+il1] + dg[j] - 2.f*a1;
        sadj[il0*64 + j] = expf(-sqrtf(fmaxf(q0, 1e-12f)));
        sadj[il1*64 + j] = expf(-sqrtf(fmaxf(q1, 1e-12f)));
    }
    __syncthreads();
    {
        int il0 = tid >> 6, o = tid & 63, il1 = il0 + 4;
        float a0 = 0.f, a1 = 0.f;
        for (int jj = 0; jj < 64; jj++) {
            float mv = Ms[o*64 + (jj ^ (o & 31))];
            a0 = fmaf(sadj[il0*64 + jj], mv, a0);
            a1 = fmaf(sadj[il1*64 + jj], mv, a1);
        }
        g_adjm[b*4096 + (r0+il0)*64 + o] = a0;
        g_adjm[b*4096 + (r0+il1)*64 + o] = a1;
    }
}

// ---------------- Kernel 4: BN stats over relu(xt + adjm[idx]) ----------------
__global__ __launch_bounds__(256) void k_stats(const int* __restrict__ idx) {
    __shared__ float am[4096];
    __shared__ float red[2048];
    __shared__ int   sidx[128];
    const int tid = threadIdx.x;
    const int P0  = blockIdx.x * 128;
    const int b   = P0 >> 14;

    for (int e = tid; e < 1024; e += 256)
        ((float4*)am)[e] = ((const float4*)(g_adjm + b*4096))[e];
    if (tid < 32) ((int4*)sidx)[tid] = ((const int4*)(idx + P0))[tid];
    __syncthreads();

    const int pr = tid >> 4, c4 = tid & 15;
    const float4* xb = (const float4*)(g_xt + (size_t)P0*CO);
    float4 s4 = make_float4(0,0,0,0), q4 = make_float4(0,0,0,0);
#pragma unroll
    for (int it = 0; it < 8; it++) {
        int px = it*16 + pr;
        int k  = sidx[px];
        float4 xv = xb[px*16 + c4];
        float4 av = ((float4*)am)[k*16 + c4];
        float v0 = fmaxf(xv.x+av.x, 0.f), v1 = fmaxf(xv.y+av.y, 0.f);
        float v2 = fmaxf(xv.z+av.z, 0.f), v3 = fmaxf(xv.w+av.w, 0.f);
        s4.x += v0; s4.y += v1; s4.z += v2; s4.w += v3;
        q4.x += v0*v0; q4.y += v1*v1; q4.z += v2*v2; q4.w += v3*v3;
    }
    ((float4*)red)[pr*16 + c4] = s4;
    ((float4*)(red + 1024))[pr*16 + c4] = q4;
    __syncthreads();
    if (tid < 64) {
        float s = 0.f, q = 0.f;
#pragma unroll
        for (int p = 0; p < 16; p++) { s += red[p*64 + tid]; q += red[1024 + p*64 + tid]; }
        atomicAdd(&g_acc[ACC_BNSUM + tid], s);
        atomicAdd(&g_acc[ACC_BNSQ  + tid], q);
    }
}

// ---------------- Kernel 5: recompute features, normalize, write out; re-zero accumulators ----------------
__global__ __launch_bounds__(256) void k_final(const int* __restrict__ idx,
                                               float* __restrict__ out,
                                               const float* __restrict__ gamma,
                                               const float* __restrict__ beta) {
    __shared__ float am[4096];      // [k][o ^ (k&31)]
    __shared__ float xts[64*128];   // [o][px ^ ((o>>2)&31)]
    const int tid = threadIdx.x;
    const int P0  = blockIdx.x * 128;
    const int b   = P0 >> 14;
    const int hw0 = P0 & (HW-1);

    // re-zero SUMS+CNT (8320 floats = 130 blocks x 64) for the next graph replay
    if (blockIdx.x < 130 && tid < 64) g_acc[blockIdx.x*64 + tid] = 0.f;

    for (int e = tid; e < 4096; e += 256) {
        int k = e >> 6, o = e & 63;
        am[k*64 + (o ^ (k & 31))] = g_adjm[b*4096 + e];
    }
    const float* xb = g_xt + ((size_t)b*HW + hw0)*CO;
    for (int e4 = tid; e4 < 2048; e4 += 256) {
        float4 v = ((const float4*)xb)[e4];
        int flat = e4*4;
        int px = flat >> 6;
        int o  = flat & 63;
        int sw = (o >> 2) & 31;
        xts[(o+0)*128 + (px^sw)] = v.x;
        xts[(o+1)*128 + (px^sw)] = v.y;
        xts[(o+2)*128 + (px^sw)] = v.z;
        xts[(o+3)*128 + (px^sw)] = v.w;
    }
    const int w = tid >> 5, lane = tid & 31;
    float sc[8], bi[8];
    const float invN = 1.f/(float)NPIX;
#pragma unroll
    for (int oo = 0; oo < 8; oo++) {
        int o = w*8 + oo;
        float mean = g_acc[ACC_BNSUM + o]*invN;
        float var  = g_acc[ACC_BNSQ  + o]*invN - mean*mean;
        float s = gamma[o]*rsqrtf(var + 1e-5f);
        sc[oo] = s; bi[oo] = beta[o] - mean*s;
    }
    __syncthreads();

    float* ob = out + (size_t)b*CO*HW + hw0;
#pragma unroll
    for (int pp = 0; pp < 4; pp++) {
        int px = lane + pp*32;
        int k  = idx[P0 + px];
        int ksw = k & 31;
#pragma unroll
        for (int oo = 0; oo < 8; oo++) {
            int o = w*8 + oo;
            float v = xts[o*128 + (px ^ ((o>>2)&31))] + am[k*64 + (o ^ ksw)];
            v = fmaxf(v, 0.f);
            ob[(size_t)o*HW + px] = fmaf(v, sc[oo], bi[oo]);
        }
    }
}

// ---------------- launch ----------------
extern "C" void kernel_launch(void* const* d_in, const int* in_sizes, int n_in,
                              void* d_out, int out_size) {
    const float* x     = (const float*)d_in[0];
    const int*   index = (const int*)  d_in[1];
    const float* Wft   = (const float*)d_in[2];
    const float* Wm    = (const float*)d_in[3];
    const float* gamma = (const float*)d_in[4];
    const float* beta  = (const float*)d_in[5];
    float* out = (float*)d_out;

    k_main <<<129, 256>>>(x, Wft, index, Wm);
    k_adjA <<<16,  256>>>();
    k_adjB <<<16,  256>>>();
    k_stats<<<256, 256>>>(index);
    k_final<<<256, 256>>>(index, out, gamma, beta);
}